// round 12
// baseline (speedup 1.0000x reference)
#include <cuda_runtime.h>
#include <cuda_fp16.h>
#include <cstdint>

// WaveletBlock fused, DWT/IDWT folded into weights:
//   feat = silu(W1'·x~ + b1),  out~ = W2'·feat + b2'
// where x~/out~ are raw interleaved 2x2-pixel vectors and
//   W1' = W1·D, W2' = Dinv·W2, b2' = Dinv·b2  (precomputed in prep).
// fp16 single-pass mma.sync. 512 CTAs x 1024 threads, whole W resident in smem.

#define C_   64
#define H_   128
#define W_   128
#define HW_  (H_*W_)

#define ARS  528          // row stride (bytes): 256 fp16 + 16B pad
#define SM_A 0            // A: 128 rows x ARS  = 67584
#define SM_W 67584        // W: 256 rows x ARS = 135168
#define SM_TOTAL 202752

#define NTHR 1024

__device__ __half g_Wh[2][256 * 256];
__device__ float  g_b2[256];

// sign table column j: coeffs of (w0,w1,w2,w3) = blocks (x1,x2,x3,x4)/(y1..y4)
__device__ __forceinline__ void fold_signs(int j, float& s1, float& s2, float& s3) {
    s1 = (j < 2) ? -1.f : 1.f;             // w1: -,-,+,+
    s2 = (j & 1) ? 1.f : -1.f;             // w2: -,+,-,+
    s3 = (j == 0 || j == 3) ? 1.f : -1.f;  // w3: +,-,-,+
}

// prep: fold butterflies into W1, W2, b2 (fp32 math, one fp16 round)
__global__ void prep_fold(const float* __restrict__ w1,
                          const float* __restrict__ w2,
                          const float* __restrict__ b2)
{
    int i = blockIdx.x * blockDim.x + threadIdx.x;   // 0..65535
    // W1': rows o (feat), cols j*64+c (x~ index)
    {
        int o = i >> 8, col = i & 255, j = col >> 6, c = col & 63;
        float a0 = w1[o * 256 +   0 + c];
        float a1 = w1[o * 256 +  64 + c];
        float a2 = w1[o * 256 + 128 + c];
        float a3 = w1[o * 256 + 192 + c];
        float s1, s2, s3; fold_signs(j, s1, s2, s3);
        g_Wh[0][o * 256 + col] =
            __float2half_rn(0.5f * (a0 + s1 * a1 + s2 * a2 + s3 * a3));
    }
    // W2': rows jo*64+c (out~ index), cols h (feat)
    {
        int row = i >> 8, h = i & 255, jo = row >> 6, c = row & 63;
        float v0 = w2[(  0 + c) * 256 + h];
        float v1 = w2[( 64 + c) * 256 + h];
        float v2 = w2[(128 + c) * 256 + h];
        float v3 = w2[(192 + c) * 256 + h];
        float s1, s2, s3; fold_signs(jo, s1, s2, s3);
        g_Wh[1][row * 256 + h] =
            __float2half_rn(0.5f * (v0 + s1 * v1 + s2 * v2 + s3 * v3));
    }
    if (i < 256) {
        int jo = i >> 6, c = i & 63;
        float s1, s2, s3; fold_signs(jo, s1, s2, s3);
        g_b2[i] = 0.5f * (b2[c] + s1 * b2[64 + c] + s2 * b2[128 + c]
                          + s3 * b2[192 + c]);
    }
}

// ---------------- helpers ----------------
__device__ __forceinline__ uint32_t smem_u32(const void* p) {
    uint32_t a;
    asm("{ .reg .u64 t; cvta.to.shared.u64 t, %1; cvt.u32.u64 %0, t; }" : "=r"(a) : "l"(p));
    return a;
}
#define LDX4(r, a) \
    asm volatile("ldmatrix.sync.aligned.m8n8.x4.shared.b16 {%0,%1,%2,%3}, [%4];" \
        : "=r"((r)[0]), "=r"((r)[1]), "=r"((r)[2]), "=r"((r)[3]) : "r"(a))
#define MMA(c, a, b0, b1) \
    asm volatile("mma.sync.aligned.m16n8k16.row.col.f32.f16.f16.f32 " \
        "{%0,%1,%2,%3},{%4,%5,%6,%7},{%8,%9},{%0,%1,%2,%3};" \
        : "+f"((c)[0]), "+f"((c)[1]), "+f"((c)[2]), "+f"((c)[3]) \
        : "r"((a)[0]), "r"((a)[1]), "r"((a)[2]), "r"((a)[3]), "r"(b0), "r"(b1))
#define CP_COMMIT() asm volatile("cp.async.commit_group;" ::: "memory")
#define CP_WAIT0()  asm volatile("cp.async.wait_group 0;" ::: "memory")

__device__ __forceinline__ uint32_t pack_h2(float a, float b) {
    __half2 h = __floats2half2_rn(a, b);
    return *reinterpret_cast<uint32_t*>(&h);
}
__device__ __forceinline__ float silu(float v) {
    return v * (1.0f / (1.0f + __expf(-v)));
}

// copy full 256x256 fp16 W into smem (row stride ARS) via cp.async
__device__ __forceinline__ void copy_W(uint32_t dstbase,
                                       const __half* __restrict__ Wg, int tid)
{
    #pragma unroll
    for (int i = 0; i < 8; ++i) {
        int id = i * NTHR + tid;           // 0..8191 (16B chunks)
        int n = id >> 5, c = id & 31;
        const __half* src = Wg + n * 256 + c * 8;
        uint32_t dst = dstbase + (uint32_t)n * ARS + c * 16;
        asm volatile("cp.async.cg.shared.global [%0], [%1], 16;" :: "r"(dst), "l"(src) : "memory");
    }
}

// barrier-free GEMM: acc[i][q] covers m = mw*32+i*16.., n = q*64 + nw*8..
// B loaded via LDX4 (n8 x k32, one per quadrant per ks-pair).
__device__ __forceinline__ void gemm_full(uint32_t sb, float acc[2][4][4],
                                          int l, int mw, int nw)
{
    const uint32_t aBase = sb + SM_A
        + (uint32_t)(mw * 32 + ((l >> 3) & 1) * 8 + (l & 7)) * ARS
        + ((l >> 4) & 1) * 16;
    const uint32_t bBase = sb + SM_W
        + (uint32_t)(nw * 8 + (l & 7)) * ARS + (uint32_t)(l >> 3) * 16;

    #pragma unroll 2
    for (int pr = 0; pr < 8; ++pr) {       // k = pr*32 .. +32
        uint32_t Bf[4][4];
        #pragma unroll
        for (int q = 0; q < 4; ++q)
            LDX4(Bf[q], bBase + (uint32_t)q * (64 * ARS) + pr * 64);
        #pragma unroll
        for (int sub = 0; sub < 2; ++sub) {
            uint32_t Af[2][4];
            #pragma unroll
            for (int i = 0; i < 2; ++i)
                LDX4(Af[i], aBase + (uint32_t)i * (16 * ARS) + (pr * 2 + sub) * 32);
            #pragma unroll
            for (int i = 0; i < 2; ++i)
                #pragma unroll
                for (int q = 0; q < 4; ++q)
                    MMA(acc[i][q], Af[i], Bf[q][2 * sub], Bf[q][2 * sub + 1]);
        }
    }
}

extern "C" __global__ void __launch_bounds__(NTHR, 1)
wavelet_mma(const float* __restrict__ x,
            const float* __restrict__ conv_b,
            float* __restrict__ out)
{
    extern __shared__ char sm[];
    const uint32_t sb = smem_u32(sm);
    const int tid = threadIdx.x;
    const int l  = tid & 31, wid = tid >> 5;
    const int nw = wid & 7,  mw  = wid >> 3;   // 8 n-warps x 4 m-warps
    const int blk = blockIdx.x;
    const int n_img = blk >> 5, p = blk & 31;
    const size_t img_off = (size_t)n_img * C_ * HW_;
    const float* xb = x + img_off + (size_t)(4 * p) * W_;

    // fetch full W1' while we pack A
    copy_W(sb + SM_W, g_Wh[0], tid);
    CP_COMMIT();

    // ---- A pack: raw x~ -> fp16 [m=128][k=256] (no butterfly) ----
    #pragma unroll
    for (int i = 0; i < 4; ++i) {
        int e = i * NTHR + tid;
        int cpair = e >> 7, m = e & 127;
        int c0 = cpair * 2, hl = m >> 6, wh = m & 63;
        const float* px = xb + (size_t)c0 * HW_ + (size_t)(2 * hl) * W_ + 2 * wh;
        float2 t0 = *(const float2*)px,         b0 = *(const float2*)(px + W_);
        float2 t1 = *(const float2*)(px + HW_), b1 = *(const float2*)(px + HW_ + W_);
        uint32_t base = (uint32_t)m * ARS + (uint32_t)c0 * 2;
        *(uint32_t*)(sm + SM_A + base      ) = pack_h2(t0.x, t1.x);  // j=0 even/even
        *(uint32_t*)(sm + SM_A + base + 128) = pack_h2(b0.x, b1.x);  // j=1 odd/even
        *(uint32_t*)(sm + SM_A + base + 256) = pack_h2(t0.y, t1.y);  // j=2 even/odd
        *(uint32_t*)(sm + SM_A + base + 384) = pack_h2(b0.y, b1.y);  // j=3 odd/odd
    }

    float acc[2][4][4];
    #pragma unroll
    for (int i = 0; i < 2; ++i)
        #pragma unroll
        for (int q = 0; q < 4; ++q)
            #pragma unroll
            for (int r = 0; r < 4; ++r) acc[i][q][r] = 0.f;

    CP_WAIT0();
    __syncthreads();

    // ---- GEMM1 ----
    gemm_full(sb, acc, l, mw, nw);

    __syncthreads();                 // all W1 / A reads done

    // fetch W2', overlapped with epilogue 1
    copy_W(sb + SM_W, g_Wh[1], tid);
    CP_COMMIT();

    // ---- epilogue 1: bias + SiLU -> A fp16 (feat) ----
    {
        float bv[4][2];
        #pragma unroll
        for (int q = 0; q < 4; ++q)
            #pragma unroll
            for (int cp = 0; cp < 2; ++cp)
                bv[q][cp] = __ldg(conv_b + q * 64 + nw * 8 + (l & 3) * 2 + cp);
        #pragma unroll
        for (int i = 0; i < 2; ++i)
            #pragma unroll
            for (int rh = 0; rh < 2; ++rh) {
                int m = mw * 32 + i * 16 + rh * 8 + (l >> 2);
                #pragma unroll
                for (int q = 0; q < 4; ++q) {
                    float v0 = silu(acc[i][q][rh * 2 + 0] + bv[q][0]);
                    float v1 = silu(acc[i][q][rh * 2 + 1] + bv[q][1]);
                    int col = q * 64 + nw * 8 + (l & 3) * 2;
                    uint32_t off = (uint32_t)m * ARS + (uint32_t)col * 2;
                    *(uint32_t*)(sm + SM_A + off) = pack_h2(v0, v1);
                }
            }
    }
    #pragma unroll
    for (int i = 0; i < 2; ++i)
        #pragma unroll
        for (int q = 0; q < 4; ++q)
            #pragma unroll
            for (int r = 0; r < 4; ++r) acc[i][q][r] = 0.f;

    CP_WAIT0();
    __syncthreads();

    // ---- GEMM2 ----
    gemm_full(sb, acc, l, mw, nw);

    // ---- epilogue 2: bias + store (IDWT folded) ----
    {
        float bv[4][2];
        #pragma unroll
        for (int q = 0; q < 4; ++q)
            #pragma unroll
            for (int cp = 0; cp < 2; ++cp)
                bv[q][cp] = g_b2[q * 64 + nw * 8 + (l & 3) * 2 + cp];
        #pragma unroll
        for (int i = 0; i < 2; ++i)
            #pragma unroll
            for (int rh = 0; rh < 2; ++rh) {
                int m = mw * 32 + i * 16 + rh * 8 + (l >> 2);
                int wh = m & 63, hl = m >> 6;
                int r0 = 4 * p + 2 * hl;
                #pragma unroll
                for (int cp = 0; cp < 2; ++cp) {
                    int co = nw * 8 + (l & 3) * 2 + cp;
                    float y0 = acc[i][0][rh * 2 + cp] + bv[0][cp];  // (r0,   even)
                    float y1 = acc[i][1][rh * 2 + cp] + bv[1][cp];  // (r0+1, even)
                    float y2 = acc[i][2][rh * 2 + cp] + bv[2][cp];  // (r0,   odd)
                    float y3 = acc[i][3][rh * 2 + cp] + bv[3][cp];  // (r0+1, odd)
                    float* po = out + img_off + (size_t)co * HW_
                              + (size_t)r0 * W_ + 2 * wh;
                    *(float2*)po        = make_float2(y0, y2);
                    *(float2*)(po + W_) = make_float2(y1, y3);
                }
            }
    }
}

extern "C" void kernel_launch(void* const* d_in, const int* in_sizes, int n_in,
                              void* d_out, int out_size)
{
    const float* x          = (const float*)d_in[0];
    const float* conv_w     = (const float*)d_in[1];
    const float* conv_b     = (const float*)d_in[2];
    const float* conv_out_w = (const float*)d_in[3];
    const float* conv_out_b = (const float*)d_in[4];
    float* out = (float*)d_out;

    prep_fold<<<256, 256>>>(conv_w, conv_out_w, conv_out_b);

    cudaFuncSetAttribute(wavelet_mma,
                         cudaFuncAttributeMaxDynamicSharedMemorySize, SM_TOTAL);
    wavelet_mma<<<512, NTHR, SM_TOTAL>>>(x, conv_b, out);
}

// round 13
// speedup vs baseline: 1.2118x; 1.2118x over previous
#include <cuda_runtime.h>
#include <cuda_fp16.h>
#include <cstdint>

// WaveletBlock fused, DWT/IDWT folded into weights:
//   feat = silu(W1'·x~ + b1),  out~ = W2'·feat + b2'
// x~/out~ are raw interleaved 2x2-pixel vectors; W1'=W1·D, W2'=Dinv·W2,
// b2'=Dinv·b2 precomputed. fp16 single-pass mma.sync.
// 512 CTAs x 1024 threads (32 warps, 8n x 4m), whole W resident in smem.
// GEMM inner loop identical to the 93us R8 kernel (LDX2 B per k-step).

#define C_   64
#define H_   128
#define W_   128
#define HW_  (H_*W_)

#define ARS  528          // row stride (bytes): 256 fp16 + 16B pad
#define SM_A 0            // A: 128 rows x ARS  = 67584
#define SM_W 67584        // W: 256 rows x ARS = 135168
#define SM_TOTAL 202752

#define NTHR 1024

__device__ __half g_Wh[2][256 * 256];
__device__ float  g_b2[256];

// sign table column j: coeffs of (w1,w2,w3) blocks
__device__ __forceinline__ void fold_signs(int j, float& s1, float& s2, float& s3) {
    s1 = (j < 2) ? -1.f : 1.f;             // -,-,+,+
    s2 = (j & 1) ? 1.f : -1.f;             // -,+,-,+
    s3 = (j == 0 || j == 3) ? 1.f : -1.f;  // +,-,-,+
}

// prep: fold butterflies into W1, W2, b2 (fp32 math, one fp16 round)
__global__ void prep_fold(const float* __restrict__ w1,
                          const float* __restrict__ w2,
                          const float* __restrict__ b2)
{
    int i = blockIdx.x * blockDim.x + threadIdx.x;   // 0..65535
    // W1': rows o (feat), cols j*64+c (x~ index)
    {
        int o = i >> 8, col = i & 255, j = col >> 6, c = col & 63;
        float a0 = w1[o * 256 +   0 + c];
        float a1 = w1[o * 256 +  64 + c];
        float a2 = w1[o * 256 + 128 + c];
        float a3 = w1[o * 256 + 192 + c];
        float s1, s2, s3; fold_signs(j, s1, s2, s3);
        g_Wh[0][o * 256 + col] =
            __float2half_rn(0.5f * (a0 + s1 * a1 + s2 * a2 + s3 * a3));
    }
    // W2': rows jo*64+c (out~ index), cols h (feat)
    {
        int row = i >> 8, h = i & 255, jo = row >> 6, c = row & 63;
        float v0 = w2[(  0 + c) * 256 + h];
        float v1 = w2[( 64 + c) * 256 + h];
        float v2 = w2[(128 + c) * 256 + h];
        float v3 = w2[(192 + c) * 256 + h];
        float s1, s2, s3; fold_signs(jo, s1, s2, s3);
        g_Wh[1][row * 256 + h] =
            __float2half_rn(0.5f * (v0 + s1 * v1 + s2 * v2 + s3 * v3));
    }
    if (i < 256) {
        int jo = i >> 6, c = i & 63;
        float s1, s2, s3; fold_signs(jo, s1, s2, s3);
        g_b2[i] = 0.5f * (b2[c] + s1 * b2[64 + c] + s2 * b2[128 + c]
                          + s3 * b2[192 + c]);
    }
}

// ---------------- helpers ----------------
__device__ __forceinline__ uint32_t smem_u32(const void* p) {
    uint32_t a;
    asm("{ .reg .u64 t; cvta.to.shared.u64 t, %1; cvt.u32.u64 %0, t; }" : "=r"(a) : "l"(p));
    return a;
}
#define LDX4(r, a) \
    asm volatile("ldmatrix.sync.aligned.m8n8.x4.shared.b16 {%0,%1,%2,%3}, [%4];" \
        : "=r"((r)[0]), "=r"((r)[1]), "=r"((r)[2]), "=r"((r)[3]) : "r"(a))
#define LDX2(r, a) \
    asm volatile("ldmatrix.sync.aligned.m8n8.x2.shared.b16 {%0,%1}, [%2];" \
        : "=r"((r)[0]), "=r"((r)[1]) : "r"(a))
#define MMA(c, a, b0, b1) \
    asm volatile("mma.sync.aligned.m16n8k16.row.col.f32.f16.f16.f32 " \
        "{%0,%1,%2,%3},{%4,%5,%6,%7},{%8,%9},{%0,%1,%2,%3};" \
        : "+f"((c)[0]), "+f"((c)[1]), "+f"((c)[2]), "+f"((c)[3]) \
        : "r"((a)[0]), "r"((a)[1]), "r"((a)[2]), "r"((a)[3]), "r"(b0), "r"(b1))
#define CP_COMMIT() asm volatile("cp.async.commit_group;" ::: "memory")
#define CP_WAIT0()  asm volatile("cp.async.wait_group 0;" ::: "memory")

__device__ __forceinline__ uint32_t pack_h2(float a, float b) {
    __half2 h = __floats2half2_rn(a, b);
    return *reinterpret_cast<uint32_t*>(&h);
}
__device__ __forceinline__ float silu(float v) {
    return v * (1.0f / (1.0f + __expf(-v)));
}

// copy full 256x256 fp16 W into smem (row stride ARS) via cp.async
__device__ __forceinline__ void copy_W(uint32_t dstbase,
                                       const __half* __restrict__ Wg, int tid)
{
    #pragma unroll
    for (int i = 0; i < 8; ++i) {
        int id = i * NTHR + tid;           // 0..8191 (16B chunks)
        int n = id >> 5, c = id & 31;
        const __half* src = Wg + n * 256 + c * 8;
        uint32_t dst = dstbase + (uint32_t)n * ARS + c * 16;
        asm volatile("cp.async.cg.shared.global [%0], [%1], 16;" :: "r"(dst), "l"(src) : "memory");
    }
}

// barrier-free GEMM (R8 pattern): acc[i][q]: m = mw*32+i*16.., n = q*64+nw*8..
__device__ __forceinline__ void gemm_full(uint32_t sb, float acc[2][4][4],
                                          int l, int mw, int nw)
{
    const uint32_t aBase = sb + SM_A
        + (uint32_t)(mw * 32 + ((l >> 3) & 1) * 8 + (l & 7)) * ARS
        + ((l >> 4) & 1) * 16;
    const int ll = l & 15;
    const uint32_t bBase = sb + SM_W
        + (uint32_t)(nw * 8 + (ll & 7)) * ARS + ((ll >> 3) & 1) * 16;

    #pragma unroll 2
    for (int ks = 0; ks < 16; ++ks) {
        uint32_t Bf[4][2], Af[2][4];
        #pragma unroll
        for (int q = 0; q < 4; ++q)
            LDX2(Bf[q], bBase + (uint32_t)q * (64 * ARS) + ks * 32);
        #pragma unroll
        for (int i = 0; i < 2; ++i)
            LDX4(Af[i], aBase + (uint32_t)i * (16 * ARS) + ks * 32);
        #pragma unroll
        for (int i = 0; i < 2; ++i)
            #pragma unroll
            for (int q = 0; q < 4; ++q)
                MMA(acc[i][q], Af[i], Bf[q][0], Bf[q][1]);
    }
}

extern "C" __global__ void __launch_bounds__(NTHR, 1)
wavelet_mma(const float* __restrict__ x,
            const float* __restrict__ conv_b,
            float* __restrict__ out)
{
    extern __shared__ char sm[];
    const uint32_t sb = smem_u32(sm);
    const int tid = threadIdx.x;
    const int l  = tid & 31, wid = tid >> 5;
    const int nw = wid & 7,  mw  = wid >> 3;   // 8 n-warps x 4 m-warps
    const int blk = blockIdx.x;
    const int n_img = blk >> 5, p = blk & 31;
    const size_t img_off = (size_t)n_img * C_ * HW_;
    const float* xb = x + img_off + (size_t)(4 * p) * W_;

    // fetch full W1' while we pack A
    copy_W(sb + SM_W, g_Wh[0], tid);
    CP_COMMIT();

    // ---- A pack: raw x~ -> fp16 [m=128][k=256] (butterfly folded away) ----
    #pragma unroll
    for (int i = 0; i < 4; ++i) {
        int e = i * NTHR + tid;
        int cpair = e >> 7, m = e & 127;
        int c0 = cpair * 2, hl = m >> 6, wh = m & 63;
        const float* px = xb + (size_t)c0 * HW_ + (size_t)(2 * hl) * W_ + 2 * wh;
        float2 t0 = *(const float2*)px,         b0 = *(const float2*)(px + W_);
        float2 t1 = *(const float2*)(px + HW_), b1 = *(const float2*)(px + HW_ + W_);
        uint32_t base = (uint32_t)m * ARS + (uint32_t)c0 * 2;
        *(uint32_t*)(sm + SM_A + base      ) = pack_h2(t0.x, t1.x);  // j=0 even/even
        *(uint32_t*)(sm + SM_A + base + 128) = pack_h2(b0.x, b1.x);  // j=1 odd/even
        *(uint32_t*)(sm + SM_A + base + 256) = pack_h2(t0.y, t1.y);  // j=2 even/odd
        *(uint32_t*)(sm + SM_A + base + 384) = pack_h2(b0.y, b1.y);  // j=3 odd/odd
    }

    float acc[2][4][4];
    #pragma unroll
    for (int i = 0; i < 2; ++i)
        #pragma unroll
        for (int q = 0; q < 4; ++q)
            #pragma unroll
            for (int r = 0; r < 4; ++r) acc[i][q][r] = 0.f;

    CP_WAIT0();
    __syncthreads();

    // ---- GEMM1 ----
    gemm_full(sb, acc, l, mw, nw);

    __syncthreads();                 // all W1 / A reads done

    // fetch W2', overlapped with epilogue 1
    copy_W(sb + SM_W, g_Wh[1], tid);
    CP_COMMIT();

    // ---- epilogue 1: bias + SiLU -> A fp16 (feat) ----
    {
        float bv[4][2];
        #pragma unroll
        for (int q = 0; q < 4; ++q)
            #pragma unroll
            for (int cp = 0; cp < 2; ++cp)
                bv[q][cp] = __ldg(conv_b + q * 64 + nw * 8 + (l & 3) * 2 + cp);
        #pragma unroll
        for (int i = 0; i < 2; ++i)
            #pragma unroll
            for (int rh = 0; rh < 2; ++rh) {
                int m = mw * 32 + i * 16 + rh * 8 + (l >> 2);
                #pragma unroll
                for (int q = 0; q < 4; ++q) {
                    float v0 = silu(acc[i][q][rh * 2 + 0] + bv[q][0]);
                    float v1 = silu(acc[i][q][rh * 2 + 1] + bv[q][1]);
                    int col = q * 64 + nw * 8 + (l & 3) * 2;
                    uint32_t off = (uint32_t)m * ARS + (uint32_t)col * 2;
                    *(uint32_t*)(sm + SM_A + off) = pack_h2(v0, v1);
                }
            }
    }
    #pragma unroll
    for (int i = 0; i < 2; ++i)
        #pragma unroll
        for (int q = 0; q < 4; ++q)
            #pragma unroll
            for (int r = 0; r < 4; ++r) acc[i][q][r] = 0.f;

    CP_WAIT0();
    __syncthreads();

    // ---- GEMM2 ----
    gemm_full(sb, acc, l, mw, nw);

    // ---- epilogue 2: bias + store (IDWT folded away) ----
    {
        float bv[4][2];
        #pragma unroll
        for (int q = 0; q < 4; ++q)
            #pragma unroll
            for (int cp = 0; cp < 2; ++cp)
                bv[q][cp] = g_b2[q * 64 + nw * 8 + (l & 3) * 2 + cp];
        #pragma unroll
        for (int i = 0; i < 2; ++i)
            #pragma unroll
            for (int rh = 0; rh < 2; ++rh) {
                int m = mw * 32 + i * 16 + rh * 8 + (l >> 2);
                int wh = m & 63, hl = m >> 6;
                int r0 = 4 * p + 2 * hl;
                #pragma unroll
                for (int cp = 0; cp < 2; ++cp) {
                    int co = nw * 8 + (l & 3) * 2 + cp;
                    float y0 = acc[i][0][rh * 2 + cp] + bv[0][cp];  // (r0,   even)
                    float y1 = acc[i][1][rh * 2 + cp] + bv[1][cp];  // (r0+1, even)
                    float y2 = acc[i][2][rh * 2 + cp] + bv[2][cp];  // (r0,   odd)
                    float y3 = acc[i][3][rh * 2 + cp] + bv[3][cp];  // (r0+1, odd)
                    float* po = out + img_off + (size_t)co * HW_
                              + (size_t)r0 * W_ + 2 * wh;
                    *(float2*)po        = make_float2(y0, y2);
                    *(float2*)(po + W_) = make_float2(y1, y3);
                }
            }
    }
}

extern "C" void kernel_launch(void* const* d_in, const int* in_sizes, int n_in,
                              void* d_out, int out_size)
{
    const float* x          = (const float*)d_in[0];
    const float* conv_w     = (const float*)d_in[1];
    const float* conv_b     = (const float*)d_in[2];
    const float* conv_out_w = (const float*)d_in[3];
    const float* conv_out_b = (const float*)d_in[4];
    float* out = (float*)d_out;

    prep_fold<<<256, 256>>>(conv_w, conv_out_w, conv_out_b);

    cudaFuncSetAttribute(wavelet_mma,
                         cudaFuncAttributeMaxDynamicSharedMemorySize, SM_TOTAL);
    wavelet_mma<<<512, NTHR, SM_TOTAL>>>(x, conv_b, out);
}

// round 15
// speedup vs baseline: 1.2997x; 1.0726x over previous
#include <cuda_runtime.h>
#include <cuda_fp16.h>
#include <cstdint>

// WaveletBlock fused, DWT/IDWT folded into weights.
// fp16 single-pass mma.sync. 1024 CTAs x 512 threads, 2 CTAs/SM.
// M_tile=64; W held as k=128 halves (69.6KB buffer), sibling-CTA overlap.

#define C_   64
#define H_   128
#define W_   128
#define HW_  (H_*W_)

#define ARS  528          // A row stride (bytes): 256 fp16 + 16B pad
#define WRS  272          // W half row stride: 128 fp16 + 16B pad
#define SM_A 0            // A: 64 x 528 = 33792
#define SM_W 33792        // W half: 256 x 272 = 69632
#define SM_TOTAL 103424

#define NTHR 512

__device__ __half g_Wh[2][256 * 256];
__device__ float  g_b2[256];

__device__ __forceinline__ void fold_signs(int j, float& s1, float& s2, float& s3) {
    s1 = (j < 2) ? -1.f : 1.f;
    s2 = (j & 1) ? 1.f : -1.f;
    s3 = (j == 0 || j == 3) ? 1.f : -1.f;
}

__global__ void prep_fold(const float* __restrict__ w1,
                          const float* __restrict__ w2,
                          const float* __restrict__ b2)
{
    int i = blockIdx.x * blockDim.x + threadIdx.x;   // 0..65535
    {
        int o = i >> 8, col = i & 255, j = col >> 6, c = col & 63;
        float a0 = w1[o * 256 +   0 + c];
        float a1 = w1[o * 256 +  64 + c];
        float a2 = w1[o * 256 + 128 + c];
        float a3 = w1[o * 256 + 192 + c];
        float s1, s2, s3; fold_signs(j, s1, s2, s3);
        g_Wh[0][o * 256 + col] =
            __float2half_rn(0.5f * (a0 + s1 * a1 + s2 * a2 + s3 * a3));
    }
    {
        int row = i >> 8, h = i & 255, jo = row >> 6, c = row & 63;
        float v0 = w2[(  0 + c) * 256 + h];
        float v1 = w2[( 64 + c) * 256 + h];
        float v2 = w2[(128 + c) * 256 + h];
        float v3 = w2[(192 + c) * 256 + h];
        float s1, s2, s3; fold_signs(jo, s1, s2, s3);
        g_Wh[1][row * 256 + h] =
            __float2half_rn(0.5f * (v0 + s1 * v1 + s2 * v2 + s3 * v3));
    }
    if (i < 256) {
        int jo = i >> 6, c = i & 63;
        float s1, s2, s3; fold_signs(jo, s1, s2, s3);
        g_b2[i] = 0.5f * (b2[c] + s1 * b2[64 + c] + s2 * b2[128 + c]
                          + s3 * b2[192 + c]);
    }
}

// ---------------- helpers ----------------
__device__ __forceinline__ uint32_t smem_u32(const void* p) {
    uint32_t a;
    asm("{ .reg .u64 t; cvta.to.shared.u64 t, %1; cvt.u32.u64 %0, t; }" : "=r"(a) : "l"(p));
    return a;
}
#define LDX4(r, a) \
    asm volatile("ldmatrix.sync.aligned.m8n8.x4.shared.b16 {%0,%1,%2,%3}, [%4];" \
        : "=r"((r)[0]), "=r"((r)[1]), "=r"((r)[2]), "=r"((r)[3]) : "r"(a))
#define LDX2(r, a) \
    asm volatile("ldmatrix.sync.aligned.m8n8.x2.shared.b16 {%0,%1}, [%2];" \
        : "=r"((r)[0]), "=r"((r)[1]) : "r"(a))
#define MMA(c, a, b0, b1) \
    asm volatile("mma.sync.aligned.m16n8k16.row.col.f32.f16.f16.f32 " \
        "{%0,%1,%2,%3},{%4,%5,%6,%7},{%8,%9},{%0,%1,%2,%3};" \
        : "+f"((c)[0]), "+f"((c)[1]), "+f"((c)[2]), "+f"((c)[3]) \
        : "r"((a)[0]), "r"((a)[1]), "r"((a)[2]), "r"((a)[3]), "r"(b0), "r"(b1))
#define CP_COMMIT() asm volatile("cp.async.commit_group;" ::: "memory")
#define CP_WAIT0()  asm volatile("cp.async.wait_group 0;" ::: "memory")

__device__ __forceinline__ uint32_t pack_h2(float a, float b) {
    __half2 h = __floats2half2_rn(a, b);
    return *reinterpret_cast<uint32_t*>(&h);
}
__device__ __forceinline__ float silu(float v) {
    return v * (1.0f / (1.0f + __expf(-v)));
}

// copy one k=128 half of a 256x256 fp16 W into the W buffer
// 256 rows x 256 bytes = 4096 16B-chunks (16 per row)
__device__ __forceinline__ void copy_W_half(uint32_t wbase,
                                            const __half* __restrict__ Wg,
                                            int half, int tid)
{
    #pragma unroll
    for (int i = 0; i < 8; ++i) {
        int id = i * NTHR + tid;           // 0..4095
        int n = id >> 4, c = id & 15;
        const __half* src = Wg + n * 256 + half * 128 + c * 8;
        uint32_t dst = wbase + (uint32_t)n * WRS + c * 16;
        asm volatile("cp.async.cg.shared.global [%0], [%1], 16;" :: "r"(dst), "l"(src) : "memory");
    }
}

// 8 k-steps against the resident W half; aOffB = half*256 bytes into A cols.
__device__ __forceinline__ void gemm_half(uint32_t sb, float acc[2][4][4],
                                          int l, int mw, int nw, uint32_t aOffB)
{
    const uint32_t aBase = sb + SM_A
        + (uint32_t)(mw * 32 + ((l >> 3) & 1) * 8 + (l & 7)) * ARS
        + ((l >> 4) & 1) * 16 + aOffB;
    const int ll = l & 15;
    const uint32_t bBase = sb + SM_W
        + (uint32_t)(nw * 8 + (ll & 7)) * WRS + ((ll >> 3) & 1) * 16;

    #pragma unroll 2
    for (int ks = 0; ks < 8; ++ks) {
        uint32_t Bf[4][2], Af[2][4];
        #pragma unroll
        for (int q = 0; q < 4; ++q)
            LDX2(Bf[q], bBase + (uint32_t)q * (64 * WRS) + ks * 32);
        #pragma unroll
        for (int i = 0; i < 2; ++i)
            LDX4(Af[i], aBase + (uint32_t)i * (16 * ARS) + ks * 32);
        #pragma unroll
        for (int i = 0; i < 2; ++i)
            #pragma unroll
            for (int q = 0; q < 4; ++q)
                MMA(acc[i][q], Af[i], Bf[q][0], Bf[q][1]);
    }
}

extern "C" __global__ void __launch_bounds__(NTHR, 2)
wavelet_mma(const float* __restrict__ x,
            const float* __restrict__ conv_b,
            float* __restrict__ out)
{
    extern __shared__ char sm[];
    const uint32_t sb = smem_u32(sm);
    const int tid = threadIdx.x;
    const int l  = tid & 31, wid = tid >> 5;
    const int nw = wid & 7,  mw  = wid >> 3;   // 8 n-warps x 2 m-warps
    const int blk = blockIdx.x;
    const int n_img = blk >> 6, hh = blk & 63;
    const size_t img_off = (size_t)n_img * C_ * HW_;
    const float* xb = x + img_off + (size_t)(2 * hh) * W_;

    // sibling de-phasing: co-resident CTAs take opposite k-half order
    const int o0 = (blk / 148) & 1, o1 = o0 ^ 1;

    // prefetch first W1 half while we pack A
    copy_W_half(sb + SM_W, g_Wh[0], o0, tid);
    CP_COMMIT();

    // ---- A pack: raw x~ -> fp16 [m=64][k=256] (butterfly folded away) ----
    #pragma unroll
    for (int i = 0; i < 4; ++i) {
        int e = i * NTHR + tid;            // 0..2047
        int cpair = e >> 6, wh = e & 63;
        int c0 = cpair * 2;
        const float* px = xb + (size_t)c0 * HW_ + 2 * wh;
        float2 t0 = *(const float2*)px,         b0 = *(const float2*)(px + W_);
        float2 t1 = *(const float2*)(px + HW_), b1 = *(const float2*)(px + HW_ + W_);
        uint32_t base = (uint32_t)wh * ARS + (uint32_t)c0 * 2;
        *(uint32_t*)(sm + SM_A + base      ) = pack_h2(t0.x, t1.x);
        *(uint32_t*)(sm + SM_A + base + 128) = pack_h2(b0.x, b1.x);
        *(uint32_t*)(sm + SM_A + base + 256) = pack_h2(t0.y, t1.y);
        *(uint32_t*)(sm + SM_A + base + 384) = pack_h2(b0.y, b1.y);
    }

    float acc[2][4][4];
    #pragma unroll
    for (int i = 0; i < 2; ++i)
        #pragma unroll
        for (int q = 0; q < 4; ++q)
            #pragma unroll
            for (int r = 0; r < 4; ++r) acc[i][q][r] = 0.f;

    CP_WAIT0();
    __syncthreads();

    // ---- GEMM1 half o0 ----
    gemm_half(sb, acc, l, mw, nw, (uint32_t)o0 * 256);
    __syncthreads();

    copy_W_half(sb + SM_W, g_Wh[0], o1, tid);
    CP_COMMIT();
    CP_WAIT0();
    __syncthreads();

    // ---- GEMM1 half o1 ----
    gemm_half(sb, acc, l, mw, nw, (uint32_t)o1 * 256);
    __syncthreads();

    copy_W_half(sb + SM_W, g_Wh[1], o0, tid);
    CP_COMMIT();

    // ---- epilogue 1: bias + SiLU -> A fp16 (feat) ----
    {
        float bv[4][2];
        #pragma unroll
        for (int q = 0; q < 4; ++q)
            #pragma unroll
            for (int cp = 0; cp < 2; ++cp)
                bv[q][cp] = __ldg(conv_b + q * 64 + nw * 8 + (l & 3) * 2 + cp);
        #pragma unroll
        for (int i = 0; i < 2; ++i)
            #pragma unroll
            for (int rh = 0; rh < 2; ++rh) {
                int m = mw * 32 + i * 16 + rh * 8 + (l >> 2);
                #pragma unroll
                for (int q = 0; q < 4; ++q) {
                    float v0 = silu(acc[i][q][rh * 2 + 0] + bv[q][0]);
                    float v1 = silu(acc[i][q][rh * 2 + 1] + bv[q][1]);
                    int col = q * 64 + nw * 8 + (l & 3) * 2;
                    uint32_t off = (uint32_t)m * ARS + (uint32_t)col * 2;
                    *(uint32_t*)(sm + SM_A + off) = pack_h2(v0, v1);
                }
            }
    }
    #pragma unroll
    for (int i = 0; i < 2; ++i)
        #pragma unroll
        for (int q = 0; q < 4; ++q)
            #pragma unroll
            for (int r = 0; r < 4; ++r) acc[i][q][r] = 0.f;

    CP_WAIT0();
    __syncthreads();

    // ---- GEMM2 half o0 ----
    gemm_half(sb, acc, l, mw, nw, (uint32_t)o0 * 256);
    __syncthreads();

    copy_W_half(sb + SM_W, g_Wh[1], o1, tid);
    CP_COMMIT();
    CP_WAIT0();
    __syncthreads();

    // ---- GEMM2 half o1 ----
    gemm_half(sb, acc, l, mw, nw, (uint32_t)o1 * 256);

    // ---- epilogue 2: bias + store (IDWT folded away) ----
    {
        float bv[4][2];
        #pragma unroll
        for (int q = 0; q < 4; ++q)
            #pragma unroll
            for (int cp = 0; cp < 2; ++cp)
                bv[q][cp] = g_b2[q * 64 + nw * 8 + (l & 3) * 2 + cp];
        const int r0 = 2 * hh;
        #pragma unroll
        for (int i = 0; i < 2; ++i)
            #pragma unroll
            for (int rh = 0; rh < 2; ++rh) {
                int wh = mw * 32 + i * 16 + rh * 8 + (l >> 2);
                #pragma unroll
                for (int cp = 0; cp < 2; ++cp) {
                    int co = nw * 8 + (l & 3) * 2 + cp;
                    float y0 = acc[i][0][rh * 2 + cp] + bv[0][cp];  // (r0,   even)
                    float y1 = acc[i][1][rh * 2 + cp] + bv[1][cp];  // (r0+1, even)
                    float y2 = acc[i][2][rh * 2 + cp] + bv[2][cp];  // (r0,   odd)
                    float y3 = acc[i][3][rh * 2 + cp] + bv[3][cp];  // (r0+1, odd)
                    float* po = out + img_off + (size_t)co * HW_
                              + (size_t)r0 * W_ + 2 * wh;
                    *(float2*)po        = make_float2(y0, y2);
                    *(float2*)(po + W_) = make_float2(y1, y3);
                }
            }
    }
}

extern "C" void kernel_launch(void* const* d_in, const int* in_sizes, int n_in,
                              void* d_out, int out_size)
{
    const float* x          = (const float*)d_in[0];
    const float* conv_w     = (const float*)d_in[1];
    const float* conv_b     = (const float*)d_in[2];
    const float* conv_out_w = (const float*)d_in[3];
    const float* conv_out_b = (const float*)d_in[4];
    float* out = (float*)d_out;

    prep_fold<<<256, 256>>>(conv_w, conv_out_w, conv_out_b);

    cudaFuncSetAttribute(wavelet_mma,
                         cudaFuncAttributeMaxDynamicSharedMemorySize, SM_TOTAL);
    wavelet_mma<<<1024, NTHR, SM_TOTAL>>>(x, conv_b, out);
}

// round 16
// speedup vs baseline: 1.3021x; 1.0018x over previous
#include <cuda_runtime.h>
#include <cuda_fp16.h>
#include <cstdint>

// WaveletBlock fused, DWT/IDWT folded into weights.
// fp16 single-pass mma.sync. 1024 CTAs x 512 threads, 2 CTAs/SM.
// M_tile=64; W streamed as k=64 quarters, double-buffered cp.async pipeline.
// Sibling CTAs process quarters in rotated order (de-phased L2 traffic).

#define C_   64
#define H_   128
#define W_   128
#define HW_  (H_*W_)

#define ARS  528          // A row stride (bytes): 256 fp16 + 16B pad
#define WRS  144          // W quarter row stride: 64 fp16 + 16B pad
#define SM_A 0            // A: 64 x 528 = 33792
#define SM_W 33792        // quarter buf: 256 x 144 = 36864
#define WBUF 36864
#define SM_TOTAL 107520   // 33792 + 2*36864

#define NTHR 512

__device__ __half g_Wh[2][256 * 256];
__device__ float  g_b2[256];

__device__ __forceinline__ void fold_signs(int j, float& s1, float& s2, float& s3) {
    s1 = (j < 2) ? -1.f : 1.f;
    s2 = (j & 1) ? 1.f : -1.f;
    s3 = (j == 0 || j == 3) ? 1.f : -1.f;
}

__global__ void prep_fold(const float* __restrict__ w1,
                          const float* __restrict__ w2,
                          const float* __restrict__ b2)
{
    int i = blockIdx.x * blockDim.x + threadIdx.x;   // 0..65535
    {
        int o = i >> 8, col = i & 255, j = col >> 6, c = col & 63;
        float a0 = w1[o * 256 +   0 + c];
        float a1 = w1[o * 256 +  64 + c];
        float a2 = w1[o * 256 + 128 + c];
        float a3 = w1[o * 256 + 192 + c];
        float s1, s2, s3; fold_signs(j, s1, s2, s3);
        g_Wh[0][o * 256 + col] =
            __float2half_rn(0.5f * (a0 + s1 * a1 + s2 * a2 + s3 * a3));
    }
    {
        int row = i >> 8, h = i & 255, jo = row >> 6, c = row & 63;
        float v0 = w2[(  0 + c) * 256 + h];
        float v1 = w2[( 64 + c) * 256 + h];
        float v2 = w2[(128 + c) * 256 + h];
        float v3 = w2[(192 + c) * 256 + h];
        float s1, s2, s3; fold_signs(jo, s1, s2, s3);
        g_Wh[1][row * 256 + h] =
            __float2half_rn(0.5f * (v0 + s1 * v1 + s2 * v2 + s3 * v3));
    }
    if (i < 256) {
        int jo = i >> 6, c = i & 63;
        float s1, s2, s3; fold_signs(jo, s1, s2, s3);
        g_b2[i] = 0.5f * (b2[c] + s1 * b2[64 + c] + s2 * b2[128 + c]
                          + s3 * b2[192 + c]);
    }
}

// ---------------- helpers ----------------
__device__ __forceinline__ uint32_t smem_u32(const void* p) {
    uint32_t a;
    asm("{ .reg .u64 t; cvta.to.shared.u64 t, %1; cvt.u32.u64 %0, t; }" : "=r"(a) : "l"(p));
    return a;
}
#define LDX4(r, a) \
    asm volatile("ldmatrix.sync.aligned.m8n8.x4.shared.b16 {%0,%1,%2,%3}, [%4];" \
        : "=r"((r)[0]), "=r"((r)[1]), "=r"((r)[2]), "=r"((r)[3]) : "r"(a))
#define LDX2(r, a) \
    asm volatile("ldmatrix.sync.aligned.m8n8.x2.shared.b16 {%0,%1}, [%2];" \
        : "=r"((r)[0]), "=r"((r)[1]) : "r"(a))
#define MMA(c, a, b0, b1) \
    asm volatile("mma.sync.aligned.m16n8k16.row.col.f32.f16.f16.f32 " \
        "{%0,%1,%2,%3},{%4,%5,%6,%7},{%8,%9},{%0,%1,%2,%3};" \
        : "+f"((c)[0]), "+f"((c)[1]), "+f"((c)[2]), "+f"((c)[3]) \
        : "r"((a)[0]), "r"((a)[1]), "r"((a)[2]), "r"((a)[3]), "r"(b0), "r"(b1))
#define CP_COMMIT() asm volatile("cp.async.commit_group;" ::: "memory")
#define CP_WAIT0()  asm volatile("cp.async.wait_group 0;" ::: "memory")
#define CP_WAIT1()  asm volatile("cp.async.wait_group 1;" ::: "memory")

__device__ __forceinline__ uint32_t pack_h2(float a, float b) {
    __half2 h = __floats2half2_rn(a, b);
    return *reinterpret_cast<uint32_t*>(&h);
}
__device__ __forceinline__ float silu(float v) {
    return v * (1.0f / (1.0f + __expf(-v)));
}

// copy one k=64 quarter (q) of a 256x256 fp16 W into a quarter buffer
// 256 rows x 128B = 2048 16B-chunks (8 per row)
__device__ __forceinline__ void copy_q(uint32_t wbase,
                                       const __half* __restrict__ Wg,
                                       int q, int tid)
{
    #pragma unroll
    for (int i = 0; i < 4; ++i) {
        int id = i * NTHR + tid;           // 0..2047
        int n = id >> 3, c = id & 7;
        const __half* src = Wg + n * 256 + q * 64 + c * 8;
        uint32_t dst = wbase + (uint32_t)n * WRS + c * 16;
        asm volatile("cp.async.cg.shared.global [%0], [%1], 16;" :: "r"(dst), "l"(src) : "memory");
    }
}

// 4 k-steps against a resident quarter; aOffB = quarter*128 bytes into A cols.
__device__ __forceinline__ void gemm_q(uint32_t wb, uint32_t sb, float acc[2][4][4],
                                       int l, int mw, int nw, uint32_t aOffB)
{
    const uint32_t aBase = sb + SM_A
        + (uint32_t)(mw * 32 + ((l >> 3) & 1) * 8 + (l & 7)) * ARS
        + ((l >> 4) & 1) * 16 + aOffB;
    const int ll = l & 15;
    const uint32_t bBase = wb
        + (uint32_t)(nw * 8 + (ll & 7)) * WRS + ((ll >> 3) & 1) * 16;

    #pragma unroll
    for (int ks = 0; ks < 4; ++ks) {
        uint32_t Bf[4][2], Af[2][4];
        #pragma unroll
        for (int q = 0; q < 4; ++q)
            LDX2(Bf[q], bBase + (uint32_t)q * (64 * WRS) + ks * 32);
        #pragma unroll
        for (int i = 0; i < 2; ++i)
            LDX4(Af[i], aBase + (uint32_t)i * (16 * ARS) + ks * 32);
        #pragma unroll
        for (int i = 0; i < 2; ++i)
            #pragma unroll
            for (int q = 0; q < 4; ++q)
                MMA(acc[i][q], Af[i], Bf[q][0], Bf[q][1]);
    }
}

// pipelined GEMM over 4 quarters; quarter order rotated by ph (sibling de-phase)
// Precondition: quarter ord(0) already issued+committed into buf0.
__device__ __forceinline__ void gemm_pipe(uint32_t sb,
                                          const __half* __restrict__ Wg,
                                          float acc[2][4][4],
                                          int tid, int l, int mw, int nw, int ph)
{
    #pragma unroll 1
    for (int p = 0; p < 4; ++p) {
        int qn = (p + 1 + ph) & 3;
        if (p < 3) {
            copy_q(sb + SM_W + ((p + 1) & 1) * WBUF, Wg, qn, tid);
            CP_COMMIT();
            CP_WAIT1();
        } else {
            CP_WAIT0();
        }
        __syncthreads();
        int qc = (p + ph) & 3;
        gemm_q(sb + SM_W + (p & 1) * WBUF, sb, acc, l, mw, nw,
               (uint32_t)qc * 128);
        __syncthreads();
    }
}

extern "C" __global__ void __launch_bounds__(NTHR, 2)
wavelet_mma(const float* __restrict__ x,
            const float* __restrict__ conv_b,
            float* __restrict__ out)
{
    extern __shared__ char sm[];
    const uint32_t sb = smem_u32(sm);
    const int tid = threadIdx.x;
    const int l  = tid & 31, wid = tid >> 5;
    const int nw = wid & 7,  mw  = wid >> 3;   // 8 n-warps x 2 m-warps
    const int blk = blockIdx.x;
    const int n_img = blk >> 6, hh = blk & 63;
    const size_t img_off = (size_t)n_img * C_ * HW_;
    const float* xb = x + img_off + (size_t)(2 * hh) * W_;

    // sibling de-phase: co-resident CTAs start 2 quarters apart
    const int ph = ((blk / 148) & 1) * 2;

    // prefetch first W1 quarter while we pack A
    copy_q(sb + SM_W, g_Wh[0], ph & 3, tid);
    CP_COMMIT();

    // ---- A pack: raw x~ -> fp16 [m=64][k=256] (butterfly folded away) ----
    #pragma unroll
    for (int i = 0; i < 4; ++i) {
        int e = i * NTHR + tid;            // 0..2047
        int cpair = e >> 6, wh = e & 63;
        int c0 = cpair * 2;
        const float* px = xb + (size_t)c0 * HW_ + 2 * wh;
        float2 t0 = *(const float2*)px,         b0 = *(const float2*)(px + W_);
        float2 t1 = *(const float2*)(px + HW_), b1 = *(const float2*)(px + HW_ + W_);
        uint32_t base = (uint32_t)wh * ARS + (uint32_t)c0 * 2;
        *(uint32_t*)(sm + SM_A + base      ) = pack_h2(t0.x, t1.x);
        *(uint32_t*)(sm + SM_A + base + 128) = pack_h2(b0.x, b1.x);
        *(uint32_t*)(sm + SM_A + base + 256) = pack_h2(t0.y, t1.y);
        *(uint32_t*)(sm + SM_A + base + 384) = pack_h2(b0.y, b1.y);
    }

    float acc[2][4][4];
    #pragma unroll
    for (int i = 0; i < 2; ++i)
        #pragma unroll
        for (int q = 0; q < 4; ++q)
            #pragma unroll
            for (int r = 0; r < 4; ++r) acc[i][q][r] = 0.f;

    // ---- GEMM1 (pipelined; first internal sync orders A-pack writes) ----
    gemm_pipe(sb, g_Wh[0], acc, tid, l, mw, nw, ph);

    // prefetch first W2 quarter into buf0 (free: last GEMM1 read was buf1)
    copy_q(sb + SM_W, g_Wh[1], ph & 3, tid);
    CP_COMMIT();

    // ---- epilogue 1: bias + SiLU -> A fp16 (feat) ----
    {
        float bv[4][2];
        #pragma unroll
        for (int q = 0; q < 4; ++q)
            #pragma unroll
            for (int cp = 0; cp < 2; ++cp)
                bv[q][cp] = __ldg(conv_b + q * 64 + nw * 8 + (l & 3) * 2 + cp);
        #pragma unroll
        for (int i = 0; i < 2; ++i)
            #pragma unroll
            for (int rh = 0; rh < 2; ++rh) {
                int m = mw * 32 + i * 16 + rh * 8 + (l >> 2);
                #pragma unroll
                for (int q = 0; q < 4; ++q) {
                    float v0 = silu(acc[i][q][rh * 2 + 0] + bv[q][0]);
                    float v1 = silu(acc[i][q][rh * 2 + 1] + bv[q][1]);
                    int col = q * 64 + nw * 8 + (l & 3) * 2;
                    uint32_t off = (uint32_t)m * ARS + (uint32_t)col * 2;
                    *(uint32_t*)(sm + SM_A + off) = pack_h2(v0, v1);
                }
            }
    }
    #pragma unroll
    for (int i = 0; i < 2; ++i)
        #pragma unroll
        for (int q = 0; q < 4; ++q)
            #pragma unroll
            for (int r = 0; r < 4; ++r) acc[i][q][r] = 0.f;

    // ---- GEMM2 (pipelined; first internal sync orders epilogue-1 writes) ----
    gemm_pipe(sb, g_Wh[1], acc, tid, l, mw, nw, ph);

    // ---- epilogue 2: bias + store (IDWT folded away) ----
    {
        float bv[4][2];
        #pragma unroll
        for (int q = 0; q < 4; ++q)
            #pragma unroll
            for (int cp = 0; cp < 2; ++cp)
                bv[q][cp] = g_b2[q * 64 + nw * 8 + (l & 3) * 2 + cp];
        const int r0 = 2 * hh;
        #pragma unroll
        for (int i = 0; i < 2; ++i)
            #pragma unroll
            for (int rh = 0; rh < 2; ++rh) {
                int wh = mw * 32 + i * 16 + rh * 8 + (l >> 2);
                #pragma unroll
                for (int cp = 0; cp < 2; ++cp) {
                    int co = nw * 8 + (l & 3) * 2 + cp;
                    float y0 = acc[i][0][rh * 2 + cp] + bv[0][cp];  // (r0,   even)
                    float y1 = acc[i][1][rh * 2 + cp] + bv[1][cp];  // (r0+1, even)
                    float y2 = acc[i][2][rh * 2 + cp] + bv[2][cp];  // (r0,   odd)
                    float y3 = acc[i][3][rh * 2 + cp] + bv[3][cp];  // (r0+1, odd)
                    float* po = out + img_off + (size_t)co * HW_
                              + (size_t)r0 * W_ + 2 * wh;
                    *(float2*)po        = make_float2(y0, y2);
                    *(float2*)(po + W_) = make_float2(y1, y3);
                }
            }
    }
}

extern "C" void kernel_launch(void* const* d_in, const int* in_sizes, int n_in,
                              void* d_out, int out_size)
{
    const float* x          = (const float*)d_in[0];
    const float* conv_w     = (const float*)d_in[1];
    const float* conv_b     = (const float*)d_in[2];
    const float* conv_out_w = (const float*)d_in[3];
    const float* conv_out_b = (const float*)d_in[4];
    float* out = (float*)d_out;

    prep_fold<<<256, 256>>>(conv_w, conv_out_w, conv_out_b);

    cudaFuncSetAttribute(wavelet_mma,
                         cudaFuncAttributeMaxDynamicSharedMemorySize, SM_TOTAL);
    wavelet_mma<<<1024, NTHR, SM_TOTAL>>>(x, conv_b, out);
}